// round 1
// baseline (speedup 1.0000x reference)
#include <cuda_runtime.h>
#include <float.h>

// Problem constants
#define BSZ 16
#define NP  4096   // positions
#define ND  256    // feature dim
#define NC  512    // channels

// Tiling
#define BN 64          // channels per block
#define BM 128         // positions per chunk
#define KT_PITCH 68    // padded pitch for transposed kernel tile (f4-aligned, low conflict)

// Per-(b,c) winning position
__device__ int g_bestidx[BSZ * NC];

// ---------------------------------------------------------------------------
// Kernel 1: zero the output (16*4096*256 floats)
// ---------------------------------------------------------------------------
__global__ void zero_kernel(float4* __restrict__ out, int n4) {
    int i = blockIdx.x * blockDim.x + threadIdx.x;
    float4 z = make_float4(0.f, 0.f, 0.f, 0.f);
    for (; i < n4; i += gridDim.x * blockDim.x) out[i] = z;
}

// ---------------------------------------------------------------------------
// Kernel 2: fused fp32 GEMM + per-channel argmax over positions.
// Grid: (NC/BN = 8, BSZ = 16). Block: 256 threads.
// Each block handles 64 channels for one batch, scanning all 4096 positions
// in chunks of 128, keeping a running (max, idx) per channel.
// ---------------------------------------------------------------------------
extern __shared__ float smem[];

__global__ __launch_bounds__(256, 1)
void argmax_kernel(const float* __restrict__ x, const float* __restrict__ kern) {
    float* xs = smem;                 // [BM][ND]          = 128*256 floats
    float* kt = smem + BM * ND;       // [ND][KT_PITCH]    = 256*68 floats (transposed kernels)

    const int b   = blockIdx.y;
    const int c0  = blockIdx.x * BN;
    const int tid = threadIdx.x;
    const int tx  = tid & 15;         // channel group: n = tx*4 .. tx*4+3
    const int ty  = tid >> 4;         // position group: m = ty*8 .. ty*8+7

    // ---- Load + transpose the 64x256 kernel tile once ----
    // 64*256/4 = 4096 float4 / 256 threads = 16 iters
    #pragma unroll
    for (int it = 0; it < 16; ++it) {
        int idx = it * 256 + tid;
        int c   = idx >> 6;           // / (ND/4)
        int kq  = idx & 63;           // % (ND/4)
        float4 v = ((const float4*)(kern + (size_t)(c0 + c) * ND))[kq];
        kt[(kq * 4 + 0) * KT_PITCH + c] = v.x;
        kt[(kq * 4 + 1) * KT_PITCH + c] = v.y;
        kt[(kq * 4 + 2) * KT_PITCH + c] = v.z;
        kt[(kq * 4 + 3) * KT_PITCH + c] = v.w;
    }

    float bestv[4];
    int   besti[4];
    #pragma unroll
    for (int j = 0; j < 4; ++j) { bestv[j] = -FLT_MAX; besti[j] = 0; }

    const float* xb = x + (size_t)b * NP * ND;

    for (int p0 = 0; p0 < NP; p0 += BM) {
        __syncthreads();   // previous-iteration xs readers done (also covers kt writes, iter 0)

        // ---- Load x chunk: 128x256 floats = 8192 float4 / 256 threads = 32 iters ----
        #pragma unroll
        for (int it = 0; it < 32; ++it) {
            int idx = it * 256 + tid;
            int m   = idx >> 6;
            int kq  = idx & 63;
            ((float4*)(xs + m * ND))[kq] =
                ((const float4*)(xb + (size_t)(p0 + m) * ND))[kq];
        }
        __syncthreads();

        // ---- 128x64 register-tiled fp32 GEMM (8x4 micro-tile per thread) ----
        float acc[8][4];
        #pragma unroll
        for (int i = 0; i < 8; ++i)
            #pragma unroll
            for (int j = 0; j < 4; ++j) acc[i][j] = 0.f;

        for (int kk = 0; kk < ND; kk += 4) {
            float4 a4[8];
            float4 b4[4];
            #pragma unroll
            for (int i = 0; i < 8; ++i)
                a4[i] = *(const float4*)(xs + (ty * 8 + i) * ND + kk);
            #pragma unroll
            for (int q = 0; q < 4; ++q)
                b4[q] = *(const float4*)(kt + (kk + q) * KT_PITCH + tx * 4);

            #pragma unroll
            for (int q = 0; q < 4; ++q) {
                float bx = b4[q].x, by = b4[q].y, bz = b4[q].z, bw = b4[q].w;
                #pragma unroll
                for (int i = 0; i < 8; ++i) {
                    float av = (q == 0) ? a4[i].x : (q == 1) ? a4[i].y
                             : (q == 2) ? a4[i].z : a4[i].w;
                    acc[i][0] += av * bx;
                    acc[i][1] += av * by;
                    acc[i][2] += av * bz;
                    acc[i][3] += av * bw;
                }
            }
        }

        // ---- Running argmax update (ascending p; strict > keeps earliest tie) ----
        #pragma unroll
        for (int i = 0; i < 8; ++i) {
            int p = p0 + ty * 8 + i;
            #pragma unroll
            for (int j = 0; j < 4; ++j) {
                if (acc[i][j] > bestv[j]) { bestv[j] = acc[i][j]; besti[j] = p; }
            }
        }
    }

    // ---- Final cross-thread (over ty) reduction per channel ----
    __syncthreads();
    float* sval = smem;                       // [16][64]
    int*   sidx = (int*)(smem + 16 * 64);     // [16][64]
    #pragma unroll
    for (int j = 0; j < 4; ++j) {
        sval[ty * 64 + tx * 4 + j] = bestv[j];
        sidx[ty * 64 + tx * 4 + j] = besti[j];
    }
    __syncthreads();
    if (tid < 64) {
        float bv = sval[tid];
        int   bi = sidx[tid];
        #pragma unroll
        for (int t = 1; t < 16; ++t) {
            float v  = sval[t * 64 + tid];
            int   ii = sidx[t * 64 + tid];
            if (v > bv || (v == bv && ii < bi)) { bv = v; bi = ii; }
        }
        // ReLU semantics: if max score <= 0, relu'd scores are all 0 -> argmax = 0
        if (bv <= 0.0f) bi = 0;
        g_bestidx[b * NC + c0 + tid] = bi;
    }
}

// ---------------------------------------------------------------------------
// Kernel 3: scatter-add kernels[c,:] into out[b, bestidx[b,c], :]
// One warp per (b,c) task; atomics handle collisions on the same position.
// ---------------------------------------------------------------------------
__global__ void scatter_kernel(const float* __restrict__ kern, float* __restrict__ out) {
    int task = blockIdx.x * 8 + (threadIdx.x >> 5);   // 1024 blocks * 8 warps = 8192
    int lane = threadIdx.x & 31;
    int b = task >> 9;            // / NC
    int c = task & (NC - 1);      // % NC
    int p = g_bestidx[task];
    float*       dst = out  + ((size_t)(b * NP + p)) * ND;
    const float* src = kern + (size_t)c * ND;
    #pragma unroll
    for (int d = lane; d < ND; d += 32)
        atomicAdd(&dst[d], src[d]);
}

// ---------------------------------------------------------------------------
extern "C" void kernel_launch(void* const* d_in, const int* in_sizes, int n_in,
                              void* d_out, int out_size) {
    const float* x    = (const float*)d_in[0];   // (16, 4096, 256) fp32
    const float* kern = (const float*)d_in[1];   // (512, 256) fp32
    float*       out  = (float*)d_out;           // (16, 4096, 256) fp32

    // Zero the output
    int n4 = BSZ * NP * ND / 4;   // 4,194,304 float4
    zero_kernel<<<4096, 256>>>((float4*)out, n4);

    // Fused GEMM + argmax
    size_t smem_bytes = (size_t)(BM * ND + ND * KT_PITCH) * sizeof(float);  // 200704
    cudaFuncSetAttribute(argmax_kernel,
                         cudaFuncAttributeMaxDynamicSharedMemorySize,
                         (int)smem_bytes);
    dim3 grid(NC / BN, BSZ);   // (8, 16) = 128 blocks
    argmax_kernel<<<grid, 256, smem_bytes>>>(x, kern);

    // Scatter-add winners
    scatter_kernel<<<BSZ * NC / 8, 256>>>(kern, out);
}